// round 7
// baseline (speedup 1.0000x reference)
#include <cuda_runtime.h>

// bicon_loss fused single kernel: 2 px/thread (float2/int2), channel-pair
// processing, HW tanh sigmoid, log-factored BCE, threadfence reduction.
// R7: half the per-thread state of the 4px version -> natural regs ~44,
// occupancy ~65% with no spills (R6 lesson: never force caps below need).

#define BB 16
#define HH 352
#define WW 352
#define HW (HH * WW)
#define WV2 (WW / 2)             // 176 vec-cols
#define NTH (BB * HH * WV2)      // 991232 threads
#define TPB 256
#define NBLK (NTH / TPB)         // 3872 exactly

__device__ float        g_part[NBLK];
__device__ unsigned int g_cnt = 0;

__device__ __forceinline__ float sigf(float x) {
    float t;
    asm("tanh.approx.f32 %0, %1;" : "=f"(t) : "f"(x * 0.5f));
    return fmaf(0.5f, t, 0.5f);
}
__device__ __forceinline__ float clipf(float v) {
    return fminf(fmaxf(v, 1e-7f), 1.0f - 1e-7f);
}

// Pair K: i=K shift (DX,DY); j=7-K shift (-DX,-DY).
// vote_i(h,w) = p_i(h,w) * p_j(h-DY, w-DX); vote_j(h,w) = p_j(h,w) * p_i(h+DY, w+DX)
template<int K, int DX, int DY>
__device__ __forceinline__ void do_pair(
    const float* __restrict__ cmb, const int* __restrict__ cnb,
    int h, bool wl, bool wr,
    float* vmax, float* vmin, float* pb0, float* pb1,
    float* pc0, float* pc1, unsigned& cntp)
{
    constexpr int CI = K;
    constexpr int CJ = 7 - K;

    const float2 xi = *(const float2*)(cmb + CI * HW);
    const float2 xj = *(const float2*)(cmb + CJ * HW);
    const int2   ti = *(const int2*)  (cnb + CI * HW);
    const int2   tj = *(const int2*)  (cnb + CJ * HW);

    const float pi[2] = { sigf(xi.x), sigf(xi.y) };
    const float pj[2] = { sigf(xj.x), sigf(xj.y) };

    float si[2], sj[2];

    if constexpr (DY != 0) {
        // si: ch CJ, row h-DY, cols w0+q-DX
        if (h > 0) {                           // DY==1 always here
            const float* nb = cmb + CJ * HW - WW;
            if constexpr (DX == 1) {
                si[0] = wl ? sigf(nb[-1]) : 0.0f;
                si[1] = sigf(nb[0]);
            } else if constexpr (DX == 0) {
                const float2 v = *(const float2*)nb;
                si[0] = sigf(v.x); si[1] = sigf(v.y);
            } else {
                si[0] = sigf(nb[1]);
                si[1] = wr ? sigf(nb[2]) : 0.0f;
            }
        } else { si[0] = si[1] = 0.0f; }

        // sj: ch CI, row h+DY, cols w0+q+DX
        if (h < HH - 1) {
            const float* nb = cmb + CI * HW + WW;
            if constexpr (DX == 1) {
                sj[0] = sigf(nb[1]);
                sj[1] = wr ? sigf(nb[2]) : 0.0f;
            } else if constexpr (DX == 0) {
                const float2 v = *(const float2*)nb;
                sj[0] = sigf(v.x); sj[1] = sigf(v.y);
            } else {
                sj[0] = wl ? sigf(nb[-1]) : 0.0f;
                sj[1] = sigf(nb[0]);
            }
        } else { sj[0] = sj[1] = 0.0f; }
    } else {
        // K==3 (DX=1, DY=0): row-h shifts reuse self sigmoids
        si[0] = wl ? sigf(cmb[CJ * HW - 1]) : 0.0f;
        si[1] = pj[0];
        sj[0] = pi[1];
        sj[1] = wr ? sigf(cmb[CI * HW + 2]) : 0.0f;
    }

    const int tia[2] = { ti.x, ti.y };
    const int tja[2] = { tj.x, tj.y };
    #pragma unroll
    for (int q = 0; q < 2; q++) {
        const float vi = pi[q] * si[q];
        const float vj = pj[q] * sj[q];
        vmax[q] = fmaxf(vmax[q], fmaxf(vi, vj));
        vmin[q] = fminf(vmin[q], fminf(vi, vj));
        const bool bi = (tia[q] != 0);
        const bool bj = (tja[q] != 0);
        cntp += ((unsigned)bi + (unsigned)bj) << (8 * q);
        pb0[q] *= clipf(bi ? vi    : 1.0f - vi);
        pb1[q] *= clipf(bj ? vj    : 1.0f - vj);
        pc0[q] *= clipf(bi ? pi[q] : 1.0f - pi[q]);
        pc1[q] *= clipf(bj ? pj[q] : 1.0f - pj[q]);
    }
}

__global__ void __launch_bounds__(TPB)
bicon_loss_kernel(const float* __restrict__ c_map,
                  const float* __restrict__ target,
                  const int*   __restrict__ con,
                  float*       __restrict__ out)
{
    const int tid  = blockIdx.x * TPB + threadIdx.x;   // grid covers NTH exactly
    const int wv   = tid % WV2;
    const int rest = tid / WV2;
    const int h    = rest % HH;
    const int b    = rest / HH;
    const int w0   = wv * 2;

    const size_t roff = (size_t)h * WW + w0;
    const float* cmb = c_map + (size_t)b * 8 * HW + roff;
    const int*   cnb = con   + (size_t)b * 8 * HW + roff;
    const bool wl = (w0 > 0);
    const bool wr = (wv < WV2 - 1);

    float vmax[2] = { -1e30f, -1e30f };
    float vmin[2] = {  1e30f,  1e30f };
    float pb0[2]  = { 1.f, 1.f };
    float pb1[2]  = { 1.f, 1.f };
    float pc0[2]  = { 1.f, 1.f };
    float pc1[2]  = { 1.f, 1.f };
    unsigned cntp = 0u;                 // 8-bit connectivity count per pixel

    // SHIFTS: k=0:(1,1)  k=1:(0,1)  k=2:(-1,1)  k=3:(1,0)
    do_pair<0,  1, 1>(cmb, cnb, h, wl, wr, vmax, vmin, pb0, pb1, pc0, pc1, cntp);
    do_pair<1,  0, 1>(cmb, cnb, h, wl, wr, vmax, vmin, pb0, pb1, pc0, pc1, cntp);
    do_pair<2, -1, 1>(cmb, cnb, h, wl, wr, vmax, vmin, pb0, pb1, pc0, pc1, cntp);
    do_pair<3,  1, 0>(cmb, cnb, h, wl, wr, vmax, vmin, pb0, pb1, pc0, pc1, cntp);

    const float2 tg2 = *(const float2*)(target + (size_t)b * HW + roff);

    float acc = 0.0f;
    #pragma unroll
    for (int q = 0; q < 2; q++) {
        const unsigned sc = (cntp >> (8 * q)) & 0xffu;
        const bool edge = (sc > 0u) && (sc < 8u);
        const float lbi  = -(__logf(pb0[q]) + __logf(pb1[q]));
        const float lcon = -(__logf(pc0[q]) + __logf(pc1[q]));
        const float d  = edge ? (1.0f - vmin[q]) : vmax[q];
        const float dc = clipf(d);
        const float tg = (q == 0) ? tg2.x : tg2.y;
        const float de = -(tg * __logf(dc) + (1.0f - tg) * __logf(1.0f - dc));
        acc += fmaf(0.8f, lcon, fmaf(0.2f, lbi, de));
    }

    // ---- block reduction ----
    #pragma unroll
    for (int o = 16; o > 0; o >>= 1)
        acc += __shfl_xor_sync(0xffffffffu, acc, o);

    __shared__ float  wsf[8];
    __shared__ double wsd[8];
    __shared__ bool   s_last;
    const int lane = threadIdx.x & 31, warp = threadIdx.x >> 5;
    if (lane == 0) wsf[warp] = acc;
    __syncthreads();
    if (warp == 0) {
        float v = (lane < 8) ? wsf[lane] : 0.0f;
        #pragma unroll
        for (int o = 4; o > 0; o >>= 1)
            v += __shfl_xor_sync(0xffffffffu, v, o);
        if (lane == 0) {
            g_part[blockIdx.x] = v;
            __threadfence();
            const unsigned c = atomicAdd(&g_cnt, 1u);
            s_last = (c == (unsigned)(NBLK - 1));
        }
    }
    __syncthreads();

    // ---- last block: deterministic final reduce in double ----
    if (s_last) {
        __threadfence();
        double v = 0.0;
        for (int i = threadIdx.x; i < NBLK; i += TPB)
            v += (double)g_part[i];
        #pragma unroll
        for (int o = 16; o > 0; o >>= 1)
            v += __shfl_xor_sync(0xffffffffu, v, o);
        if (lane == 0) wsd[warp] = v;
        __syncthreads();
        if (warp == 0) {
            double t = (lane < 8) ? wsd[lane] : 0.0;
            #pragma unroll
            for (int o = 4; o > 0; o >>= 1)
                t += __shfl_xor_sync(0xffffffffu, t, o);
            if (lane == 0) {
                out[0] = (float)t;
                __threadfence();
                g_cnt = 0;   // reset for next graph replay
            }
        }
    }
}

extern "C" void kernel_launch(void* const* d_in, const int* in_sizes, int n_in,
                              void* d_out, int out_size)
{
    const float* c_map  = (const float*)d_in[0];
    const float* target = (const float*)d_in[1];
    const int*   con    = (const int*)  d_in[2];
    bicon_loss_kernel<<<NBLK, TPB>>>(c_map, target, con, (float*)d_out);
}

// round 8
// speedup vs baseline: 1.3021x; 1.3021x over previous
#include <cuda_runtime.h>

// bicon_loss fused single kernel, R8:
//  - 4 px/thread (float4), channel-pair processing (R5 base, best so far)
//  - con loads front-batched (8x int4, __ldcs streaming) -> one 32-bit mask
//  - edge computed BEFORE vote loop -> single signed min/max accumulator
//  - HW tanh sigmoid, log-factored BCE, threadfence reduction.

#define BB 16
#define HH 352
#define WW 352
#define HW (HH * WW)
#define WV (WW / 4)              // 88 vec-cols
#define NTH (BB * HH * WV)       // 495616 threads
#define TPB 256
#define NBLK (NTH / TPB)         // 1936 exactly

__device__ float        g_part[NBLK];
__device__ unsigned int g_cnt = 0;

__device__ __forceinline__ float sigf(float x) {
    float t;
    asm("tanh.approx.f32 %0, %1;" : "=f"(t) : "f"(x * 0.5f));
    return fmaf(0.5f, t, 0.5f);
}
__device__ __forceinline__ float clipf(float v) {
    return fminf(fmaxf(v, 1e-7f), 1.0f - 1e-7f);
}

// Pair K: i=K shift (DX,DY); j=7-K shift (-DX,-DY).
// vote_i(h,w) = p_i(h,w) * p_j(h-DY, w-DX); vote_j(h,w) = p_j(h,w) * p_i(h+DY, w+DX)
// mask bit for (channel c, pixel q) = (m >> (c + 8q)) & 1
template<int K, int DX, int DY>
__device__ __forceinline__ void do_pair(
    const float* __restrict__ cmb,
    int h, bool wl, bool wr, unsigned m,
    const float* sgn, float* dacc,
    float* pb0, float* pb1, float* pc0, float* pc1)
{
    constexpr int CI = K;
    constexpr int CJ = 7 - K;

    const float4 xi = *(const float4*)(cmb + CI * HW);
    const float4 xj = *(const float4*)(cmb + CJ * HW);
    const float pi[4] = { sigf(xi.x), sigf(xi.y), sigf(xi.z), sigf(xi.w) };
    const float pj[4] = { sigf(xj.x), sigf(xj.y), sigf(xj.z), sigf(xj.w) };

    float si[4], sj[4];

    if constexpr (DY != 0) {
        if (h > 0) {                          // ch CJ, row h-1, cols w0+q-DX
            const float* nb = cmb + CJ * HW - WW;
            const float4 v = *(const float4*)nb;
            if constexpr (DX == 1) {
                si[0] = wl ? sigf(nb[-1]) : 0.0f;
                si[1] = sigf(v.x); si[2] = sigf(v.y); si[3] = sigf(v.z);
            } else if constexpr (DX == 0) {
                si[0] = sigf(v.x); si[1] = sigf(v.y);
                si[2] = sigf(v.z); si[3] = sigf(v.w);
            } else {
                si[0] = sigf(v.y); si[1] = sigf(v.z); si[2] = sigf(v.w);
                si[3] = wr ? sigf(nb[4]) : 0.0f;
            }
        } else { si[0] = si[1] = si[2] = si[3] = 0.0f; }

        if (h < HH - 1) {                     // ch CI, row h+1, cols w0+q+DX
            const float* nb = cmb + CI * HW + WW;
            const float4 v = *(const float4*)nb;
            if constexpr (DX == 1) {
                sj[0] = sigf(v.y); sj[1] = sigf(v.z); sj[2] = sigf(v.w);
                sj[3] = wr ? sigf(nb[4]) : 0.0f;
            } else if constexpr (DX == 0) {
                sj[0] = sigf(v.x); sj[1] = sigf(v.y);
                sj[2] = sigf(v.z); sj[3] = sigf(v.w);
            } else {
                sj[0] = wl ? sigf(nb[-1]) : 0.0f;
                sj[1] = sigf(v.x); sj[2] = sigf(v.y); sj[3] = sigf(v.z);
            }
        } else { sj[0] = sj[1] = sj[2] = sj[3] = 0.0f; }
    } else {
        // K==3 (DX=1, DY=0): row-h shifts reuse self sigmoids
        si[0] = wl ? sigf(cmb[CJ * HW - 1]) : 0.0f;
        si[1] = pj[0]; si[2] = pj[1]; si[3] = pj[2];
        sj[0] = pi[1]; sj[1] = pi[2]; sj[2] = pi[3];
        sj[3] = wr ? sigf(cmb[CI * HW + 4]) : 0.0f;
    }

    #pragma unroll
    for (int q = 0; q < 4; q++) {
        const float vi = pi[q] * si[q];
        const float vj = pj[q] * sj[q];
        // signed accumulator: edge -> tracks -min, else -> tracks max
        dacc[q] = fmaxf(dacc[q], fmaxf(sgn[q] * vi, sgn[q] * vj));
        const bool bi = (m >> (CI + 8 * q)) & 1u;
        const bool bj = (m >> (CJ + 8 * q)) & 1u;
        pb0[q] *= clipf(bi ? vi    : 1.0f - vi);
        pb1[q] *= clipf(bj ? vj    : 1.0f - vj);
        pc0[q] *= clipf(bi ? pi[q] : 1.0f - pi[q]);
        pc1[q] *= clipf(bj ? pj[q] : 1.0f - pj[q]);
    }
}

__global__ void __launch_bounds__(TPB, 4)
bicon_loss_kernel(const float* __restrict__ c_map,
                  const float* __restrict__ target,
                  const int*   __restrict__ con,
                  float*       __restrict__ out)
{
    const int tid  = blockIdx.x * TPB + threadIdx.x;   // grid covers NTH exactly
    const int wv   = tid % WV;
    const int rest = tid / WV;
    const int h    = rest % HH;
    const int b    = rest / HH;
    const int w0   = wv * 4;

    const size_t roff = (size_t)h * WW + w0;
    const float* cmb = c_map + (size_t)b * 8 * HW + roff;
    const int*   cnb = con   + (size_t)b * 8 * HW + roff;
    const bool wl = (w0 > 0);
    const bool wr = (wv < WV - 1);

    // ---- front-batched con loads: 8 independent int4 (streaming) -> 1 mask ----
    unsigned m = 0u;
    #pragma unroll
    for (int c = 0; c < 8; c++) {
        const int4 t = __ldcs((const int4*)(cnb + c * HW));
        m |= ((unsigned)(t.x != 0) << (c + 0))
           | ((unsigned)(t.y != 0) << (c + 8))
           | ((unsigned)(t.z != 0) << (c + 16))
           | ((unsigned)(t.w != 0) << (c + 24));
    }
    const float4 tg4 = __ldcs((const float4*)(target + (size_t)b * HW + roff));

    // edge per pixel known BEFORE the vote loop
    bool edge[4];
    float sgn[4], dacc[4];
    #pragma unroll
    for (int q = 0; q < 4; q++) {
        const int sc = __popc((m >> (8 * q)) & 0xffu);
        edge[q] = (sc > 0) && (sc < 8);
        sgn[q]  = edge[q] ? -1.0f : 1.0f;
        dacc[q] = -1e30f;
    }

    float pb0[4] = { 1.f, 1.f, 1.f, 1.f };
    float pb1[4] = { 1.f, 1.f, 1.f, 1.f };
    float pc0[4] = { 1.f, 1.f, 1.f, 1.f };
    float pc1[4] = { 1.f, 1.f, 1.f, 1.f };

    // SHIFTS: k=0:(1,1)  k=1:(0,1)  k=2:(-1,1)  k=3:(1,0)
    do_pair<0,  1, 1>(cmb, h, wl, wr, m, sgn, dacc, pb0, pb1, pc0, pc1);
    do_pair<1,  0, 1>(cmb, h, wl, wr, m, sgn, dacc, pb0, pb1, pc0, pc1);
    do_pair<2, -1, 1>(cmb, h, wl, wr, m, sgn, dacc, pb0, pb1, pc0, pc1);
    do_pair<3,  1, 0>(cmb, h, wl, wr, m, sgn, dacc, pb0, pb1, pc0, pc1);

    float acc = 0.0f;
    #pragma unroll
    for (int q = 0; q < 4; q++) {
        const float lbi  = -(__logf(pb0[q]) + __logf(pb1[q]));
        const float lcon = -(__logf(pc0[q]) + __logf(pc1[q]));
        // edge: dacc = -vmin -> d = 1 - vmin = 1 + dacc ; else d = vmax = dacc
        const float d  = edge[q] ? (1.0f + dacc[q]) : dacc[q];
        const float dc = clipf(d);
        const float tg = (q == 0) ? tg4.x : (q == 1) ? tg4.y : (q == 2) ? tg4.z : tg4.w;
        const float de = -(tg * __logf(dc) + (1.0f - tg) * __logf(1.0f - dc));
        acc += fmaf(0.8f, lcon, fmaf(0.2f, lbi, de));
    }

    // ---- block reduction ----
    #pragma unroll
    for (int o = 16; o > 0; o >>= 1)
        acc += __shfl_xor_sync(0xffffffffu, acc, o);

    __shared__ float  wsf[8];
    __shared__ double wsd[8];
    __shared__ bool   s_last;
    const int lane = threadIdx.x & 31, warp = threadIdx.x >> 5;
    if (lane == 0) wsf[warp] = acc;
    __syncthreads();
    if (warp == 0) {
        float v = (lane < 8) ? wsf[lane] : 0.0f;
        #pragma unroll
        for (int o = 4; o > 0; o >>= 1)
            v += __shfl_xor_sync(0xffffffffu, v, o);
        if (lane == 0) {
            g_part[blockIdx.x] = v;
            __threadfence();
            const unsigned c = atomicAdd(&g_cnt, 1u);
            s_last = (c == (unsigned)(NBLK - 1));
        }
    }
    __syncthreads();

    // ---- last block: deterministic final reduce in double ----
    if (s_last) {
        __threadfence();
        double v = 0.0;
        for (int i = threadIdx.x; i < NBLK; i += TPB)
            v += (double)g_part[i];
        #pragma unroll
        for (int o = 16; o > 0; o >>= 1)
            v += __shfl_xor_sync(0xffffffffu, v, o);
        if (lane == 0) wsd[warp] = v;
        __syncthreads();
        if (warp == 0) {
            double t = (lane < 8) ? wsd[lane] : 0.0;
            #pragma unroll
            for (int o = 4; o > 0; o >>= 1)
                t += __shfl_xor_sync(0xffffffffu, t, o);
            if (lane == 0) {
                out[0] = (float)t;
                __threadfence();
                g_cnt = 0;   // reset for next graph replay
            }
        }
    }
}

extern "C" void kernel_launch(void* const* d_in, const int* in_sizes, int n_in,
                              void* d_out, int out_size)
{
    const float* c_map  = (const float*)d_in[0];
    const float* target = (const float*)d_in[1];
    const int*   con    = (const int*)  d_in[2];
    bicon_loss_kernel<<<NBLK, TPB>>>(c_map, target, con, (float*)d_out);
}